// round 1
// baseline (speedup 1.0000x reference)
#include <cuda_runtime.h>
#include <cstdint>

#define BT 16384
#define Dm 1024
#define E  16
#define KN 1024          // k_nodes = BT / E
#define K2 2048          // 2*Dm (stacked real|imag)
#define RES_N (BT * Dm * 2)   // 33,554,432 floats

// ---------------- scratch (device globals; no runtime allocation) ----------
__device__ float g_scores[BT * E];                       // [t][e]
__device__ int   g_tidx[KN * E];                         // [kk][e]
__device__ float g_tsc [KN * E];                         // [kk][e]
__device__ float g_counts[BT];
__device__ float g_A [(size_t)E * KN * K2];              // per-expert A2 = [x_r | x_i]
__device__ float g_W2[(size_t)E * K2 * K2];              // per-expert [[wr, wi],[-wi, wr]]
__device__ float g_Y [(size_t)E * KN * K2];              // per-expert [y_r | y_i]

// ---------------- 1) gating scores: [BT,2048] @ [2048,16] ------------------
__global__ void gate_kernel(const float* __restrict__ x,
                            const float* __restrict__ gw) {
    int tid = blockIdx.x * blockDim.x + threadIdx.x;   // BT*E threads
    int e = tid & (E - 1);
    int t = tid >> 4;
    const float* xr = x + (size_t)t * K2;
    float acc = 0.f;
#pragma unroll 8
    for (int j = 0; j < K2; j++)
        acc += xr[j] * gw[j * E + e];
    g_scores[t * E + e] = acc;
}

// ---------------- 2) per-expert top-k (bitonic, jax tie-breaking) ----------
__global__ void topk_kernel() {
    extern __shared__ unsigned long long key[];   // 16384 * 8B = 128 KB
    const int e = blockIdx.x;
    const int tid = threadIdx.x;
    const int n = BT;

    for (int i = tid; i < n; i += blockDim.x) {
        float sc = g_scores[i * E + e];
        unsigned u = __float_as_uint(sc);
        u = (u & 0x80000000u) ? ~u : (u | 0x80000000u);   // monotone map
        // ascending key == descending score, ties -> ascending index
        key[i] = ((unsigned long long)(~u) << 32) | (unsigned)i;
    }
    __syncthreads();

    for (int k = 2; k <= n; k <<= 1) {
        for (int j = k >> 1; j > 0; j >>= 1) {
            for (int i = tid; i < n; i += blockDim.x) {
                int l = i ^ j;
                if (l > i) {
                    unsigned long long a = key[i], b = key[l];
                    bool up = ((i & k) == 0);
                    if (up ? (a > b) : (a < b)) { key[i] = b; key[l] = a; }
                }
            }
            __syncthreads();
        }
    }

    for (int kk = tid; kk < KN; kk += blockDim.x) {
        int idx = (int)(key[kk] & 0xFFFFFFFFull);
        g_tidx[kk * E + e] = idx;
        g_tsc [kk * E + e] = g_scores[idx * E + e];
    }
}

// ---------------- 3) counts ------------------------------------------------
__global__ void counts_zero_kernel() {
    int i = blockIdx.x * blockDim.x + threadIdx.x;
    if (i < BT) g_counts[i] = 0.f;
}
__global__ void counts_add_kernel() {
    int i = blockIdx.x * blockDim.x + threadIdx.x;
    if (i < KN * E) atomicAdd(&g_counts[g_tidx[i]], 1.0f);
}

// ---------------- 4) gather tokens into A2 ---------------------------------
__global__ void gather_kernel(const float* __restrict__ x) {
    int p  = blockIdx.x;              // p = kk*E + e? No: use e*KN + kk layout
    int e  = p >> 10;                 // p = e*KN + kk
    int kk = p & (KN - 1);
    int t  = g_tidx[kk * E + e];
    const float2* xr = (const float2*)(x + (size_t)t * K2);
    float* dst = g_A + ((size_t)e * KN + kk) * K2;
#pragma unroll
    for (int it = 0; it < Dm / 256; it++) {
        int d = threadIdx.x + it * 256;
        float2 v = xr[d];
        dst[d]       = v.x;
        dst[Dm + d]  = v.y;
    }
}

// ---------------- 5) build W2 = [[wr, wi],[-wi, wr]] ------------------------
__global__ void w2_kernel(const float* __restrict__ ew) {
    size_t i = (size_t)blockIdx.x * blockDim.x + threadIdx.x;  // E*Dm*Dm
    int f = (int)(i % Dm);
    int d = (int)((i / Dm) % Dm);
    int e = (int)(i / ((size_t)Dm * Dm));
    float2 w = ((const float2*)ew)[i];
    float* b = g_W2 + (size_t)e * K2 * K2;
    b[(size_t)d * K2 + f]               =  w.x;
    b[(size_t)d * K2 + Dm + f]          =  w.y;
    b[(size_t)(Dm + d) * K2 + f]        = -w.y;
    b[(size_t)(Dm + d) * K2 + Dm + f]   =  w.x;
}

// ---------------- 6) grouped GEMM: Y2 = A2 @ W2, per expert -----------------
// M=1024, N=2048, K=2048. 128x128 block tile, BK=8, 256 thr, 8x8 per thread.
__global__ void __launch_bounds__(256) gemm_kernel() {
    const int e = blockIdx.z;
    const float* __restrict__ A = g_A  + (size_t)e * KN * K2;
    const float* __restrict__ B = g_W2 + (size_t)e * K2 * K2;
    float*       __restrict__ C = g_Y  + (size_t)e * KN * K2;

    const int bm = blockIdx.y * 128;
    const int bn = blockIdx.x * 128;

    __shared__ float As[8][128];
    __shared__ float Bs[8][128];

    const int tid = threadIdx.x;
    const int tx = tid & 15;          // 0..15 -> N
    const int ty = tid >> 4;          // 0..15 -> M

    const int arow = tid >> 1, acol = (tid & 1) * 4;   // A: 128 rows x 8 k
    const int brow = tid >> 5, bcol = (tid & 31) * 4;  // B: 8 rows x 128 n

    float acc[8][8];
#pragma unroll
    for (int i = 0; i < 8; i++)
#pragma unroll
        for (int j = 0; j < 8; j++) acc[i][j] = 0.f;

    for (int k0 = 0; k0 < K2; k0 += 8) {
        float4 av = *(const float4*)(A + (size_t)(bm + arow) * K2 + k0 + acol);
        As[acol + 0][arow] = av.x;
        As[acol + 1][arow] = av.y;
        As[acol + 2][arow] = av.z;
        As[acol + 3][arow] = av.w;
        *(float4*)&Bs[brow][bcol] =
            *(const float4*)(B + (size_t)(k0 + brow) * K2 + bn + bcol);
        __syncthreads();

#pragma unroll
        for (int kk = 0; kk < 8; kk++) {
            float a[8], b[8];
            *(float4*)(a)     = *(const float4*)&As[kk][ty * 8];
            *(float4*)(a + 4) = *(const float4*)&As[kk][ty * 8 + 4];
            *(float4*)(b)     = *(const float4*)&Bs[kk][tx * 8];
            *(float4*)(b + 4) = *(const float4*)&Bs[kk][tx * 8 + 4];
#pragma unroll
            for (int i = 0; i < 8; i++)
#pragma unroll
                for (int j = 0; j < 8; j++)
                    acc[i][j] += a[i] * b[j];
        }
        __syncthreads();
    }

#pragma unroll
    for (int i = 0; i < 8; i++) {
        float* cr = C + (size_t)(bm + ty * 8 + i) * K2 + bn + tx * 8;
        *(float4*)(cr)     = *(float4*)&acc[i][0];
        *(float4*)(cr + 4) = *(float4*)&acc[i][4];
    }
}

// ---------------- 7) scale + scatter-add ------------------------------------
__global__ void scatter_kernel(float* __restrict__ out) {
    int p  = blockIdx.x;              // e*KN + kk
    int e  = p >> 10;
    int kk = p & (KN - 1);
    int t  = g_tidx[kk * E + e];
    float s = g_tsc[kk * E + e];
    const float* y = g_Y + ((size_t)e * KN + kk) * K2;
    float* o = out + (size_t)t * K2;
#pragma unroll
    for (int it = 0; it < Dm / 256; it++) {
        int f = threadIdx.x + it * 256;
        atomicAdd(&o[2 * f    ], y[f]      * s);
        atomicAdd(&o[2 * f + 1], y[Dm + f] * s);
    }
}

// ---------------- 8) divide by counts + ModReLU (in place) ------------------
__global__ void finalize_kernel(float* __restrict__ out,
                                const float* __restrict__ bias) {
    size_t i = (size_t)blockIdx.x * blockDim.x + threadIdx.x;  // BT*Dm
    int t = (int)(i / Dm);
    int d = (int)(i % Dm);
    float2 z = ((float2*)out)[i];
    float c = fmaxf(g_counts[t], 1.0f);
    z.x /= c; z.y /= c;
    float mag = sqrtf(z.x * z.x + z.y * z.y);
    float act = fmaxf(mag + bias[d], 0.0f);
    float inv = act / fmaxf(mag, 1e-8f);
    z.x *= inv; z.y *= inv;
    ((float2*)out)[i] = z;
}

// ---------------- 9) optional extra outputs (idx, scores, counts) -----------
__global__ void extras_kernel(float* __restrict__ out, int avail) {
    int i = blockIdx.x * blockDim.x + threadIdx.x;
    float* ex = out + RES_N;
    if (i < KN * E && i < avail)                 ex[i] = (float)g_tidx[i];
    if (i < KN * E && KN * E + i < avail)        ex[KN * E + i] = g_tsc[i];
    if (i < BT    && 2 * KN * E + i < avail)     ex[2 * KN * E + i] = g_counts[i];
}

// ---------------------------------------------------------------------------
extern "C" void kernel_launch(void* const* d_in, const int* in_sizes, int n_in,
                              void* d_out, int out_size) {
    const float* x    = (const float*)d_in[0];   // [BT, Dm, 2]
    const float* gw   = (const float*)d_in[1];   // [2048, 16]
    const float* ew   = (const float*)d_in[2];   // [E, Dm, Dm, 2]
    const float* bias = (const float*)d_in[3];   // [Dm]
    float* out = (float*)d_out;

    cudaMemsetAsync(d_out, 0, (size_t)RES_N * sizeof(float), 0);

    gate_kernel<<<(BT * E) / 256, 256>>>(x, gw);

    cudaFuncSetAttribute(topk_kernel,
                         cudaFuncAttributeMaxDynamicSharedMemorySize, 131072);
    topk_kernel<<<E, 1024, 131072>>>();

    counts_zero_kernel<<<BT / 256, 256>>>();
    counts_add_kernel<<<(KN * E) / 256, 256>>>();

    gather_kernel<<<E * KN, 256>>>(x);
    w2_kernel<<<(E * Dm * Dm) / 256, 256>>>(ew);

    gemm_kernel<<<dim3(K2 / 128, KN / 128, E), 256>>>();

    scatter_kernel<<<E * KN, 256>>>(out);
    finalize_kernel<<<(BT * Dm) / 256, 256>>>(out, bias);

    if (out_size > RES_N) {
        int avail = out_size - RES_N;
        extras_kernel<<<(BT + 255) / 256, 256>>>(out, avail);
    }
}

// round 3
// speedup vs baseline: 2.3045x; 2.3045x over previous
#include <cuda_runtime.h>
#include <cuda_bf16.h>
#include <cstdint>

#define BT 16384
#define Dm 1024
#define E  16
#define KN 1024          // k_nodes = BT / E
#define K2 2048          // 2*Dm (stacked real|imag)
#define RES_N (BT * Dm * 2)

// GEMM tiling
#define BM 128
#define BN 128
#define BK 64            // bf16 per k-chunk (128 B rows, SW128)
#define NSTAGE 3
#define NCHUNK 96        // 3 precision passes * (2048 / 64)
#define STAGE_BYTES 32768   // A 16KB + B 16KB
#define A_TILE_B 16384

// ---------------- scratch (device globals) ----------------------------------
__device__ float g_scores[BT * E];
__device__ int   g_tidx[KN * E];
__device__ float g_tsc [KN * E];
__device__ float g_counts[BT];
__device__ __nv_bfloat16 g_Ah[(size_t)E * KN * K2];   // [e][kk][k]  hi
__device__ __nv_bfloat16 g_Al[(size_t)E * KN * K2];   //             lo
__device__ __nv_bfloat16 g_Wh[(size_t)E * K2 * K2];   // [e][n][k]   hi (K-major)
__device__ __nv_bfloat16 g_Wl[(size_t)E * K2 * K2];   //             lo

// ---------------- helpers -----------------------------------------------------
__device__ __forceinline__ uint32_t smem_u32(const void* p) {
    uint32_t a;
    asm("{ .reg .u64 t; cvta.to.shared.u64 t, %1; cvt.u32.u64 %0, t; }"
        : "=r"(a) : "l"(p));
    return a;
}
__device__ __forceinline__ uint32_t swz(uint32_t off) {   // SW128
    return off ^ ((off >> 3) & 0x70);
}
__device__ __forceinline__ void ldsm4(uint32_t* r, uint32_t addr) {
    asm volatile("ldmatrix.sync.aligned.m8n8.x4.shared.b16 {%0,%1,%2,%3}, [%4];"
                 : "=r"(r[0]), "=r"(r[1]), "=r"(r[2]), "=r"(r[3]) : "r"(addr));
}
__device__ __forceinline__ void mma16816(float* c, const uint32_t* a,
                                         const uint32_t* b) {
    asm volatile(
        "mma.sync.aligned.m16n8k16.row.col.f32.bf16.bf16.f32 "
        "{%0,%1,%2,%3}, {%4,%5,%6,%7}, {%8,%9}, {%0,%1,%2,%3};"
        : "+f"(c[0]), "+f"(c[1]), "+f"(c[2]), "+f"(c[3])
        : "r"(a[0]), "r"(a[1]), "r"(a[2]), "r"(a[3]), "r"(b[0]), "r"(b[1]));
}

// ---------------- 1) gating scores ------------------------------------------
__global__ void gate_kernel(const float* __restrict__ x,
                            const float* __restrict__ gw) {
    int tid = blockIdx.x * blockDim.x + threadIdx.x;
    int e = tid & (E - 1);
    int t = tid >> 4;
    const float* xr = x + (size_t)t * K2;
    float acc = 0.f;
#pragma unroll 8
    for (int j = 0; j < K2; j++)
        acc += xr[j] * gw[j * E + e];
    g_scores[t * E + e] = acc;
}

// ---------------- 2) per-expert top-k (bitonic, jax ties) --------------------
__global__ void topk_kernel() {
    extern __shared__ unsigned long long key[];
    const int e = blockIdx.x;
    const int tid = threadIdx.x;
    const int n = BT;
    for (int i = tid; i < n; i += blockDim.x) {
        float sc = g_scores[i * E + e];
        unsigned u = __float_as_uint(sc);
        u = (u & 0x80000000u) ? ~u : (u | 0x80000000u);
        key[i] = ((unsigned long long)(~u) << 32) | (unsigned)i;
    }
    __syncthreads();
    for (int k = 2; k <= n; k <<= 1) {
        for (int j = k >> 1; j > 0; j >>= 1) {
            for (int i = tid; i < n; i += blockDim.x) {
                int l = i ^ j;
                if (l > i) {
                    unsigned long long a = key[i], b = key[l];
                    bool up = ((i & k) == 0);
                    if (up ? (a > b) : (a < b)) { key[i] = b; key[l] = a; }
                }
            }
            __syncthreads();
        }
    }
    for (int kk = tid; kk < KN; kk += blockDim.x) {
        int idx = (int)(key[kk] & 0xFFFFFFFFull);
        g_tidx[kk * E + e] = idx;
        g_tsc [kk * E + e] = g_scores[idx * E + e];
    }
}

// ---------------- 3) counts --------------------------------------------------
__global__ void counts_zero_kernel() {
    int i = blockIdx.x * blockDim.x + threadIdx.x;
    if (i < BT) g_counts[i] = 0.f;
}
__global__ void counts_add_kernel() {
    int i = blockIdx.x * blockDim.x + threadIdx.x;
    if (i < KN * E) atomicAdd(&g_counts[g_tidx[i]], 1.0f);
}

// ---------------- 4) gather tokens -> A hi/lo --------------------------------
__global__ void build_A_kernel(const float* __restrict__ x) {
    int p  = blockIdx.x;              // e*KN + kk
    int e  = p >> 10;
    int kk = p & (KN - 1);
    int t  = g_tidx[kk * E + e];
    const float2* xr = (const float2*)(x + (size_t)t * K2);
    size_t base = ((size_t)e * KN + kk) * K2;
#pragma unroll
    for (int it = 0; it < Dm / 256; it++) {
        int d = threadIdx.x + it * 256;
        float2 v = xr[d];
        __nv_bfloat16 hr = __float2bfloat16(v.x);
        __nv_bfloat16 lr = __float2bfloat16(v.x - __bfloat162float(hr));
        __nv_bfloat16 hi = __float2bfloat16(v.y);
        __nv_bfloat16 li = __float2bfloat16(v.y - __bfloat162float(hi));
        g_Ah[base + d]      = hr;
        g_Ah[base + Dm + d] = hi;
        g_Al[base + d]      = lr;
        g_Al[base + Dm + d] = li;
    }
}

// ---------------- 5) W2^T hi/lo via tiled transpose ---------------------------
// B[n][k]: n=f -> (w_r[d][f], -w_i[d][f]); n=1024+f -> (w_i[d][f], w_r[d][f])
__global__ void build_W_kernel(const float* __restrict__ ew) {
    __shared__ float2 tile[32][33];
    int e  = blockIdx.z;
    int d0 = blockIdx.y * 32;
    int f0 = blockIdx.x * 32;
    const float2* src = (const float2*)ew + ((size_t)e * Dm + d0) * Dm + f0;
#pragma unroll
    for (int i = threadIdx.y; i < 32; i += 8)
        tile[i][threadIdx.x] = src[(size_t)i * Dm + threadIdx.x];
    __syncthreads();
    size_t wb = (size_t)e * K2 * K2;
    int d = d0 + threadIdx.x;
#pragma unroll
    for (int i = threadIdx.y; i < 32; i += 8) {
        int f = f0 + i;
        float2 w = tile[threadIdx.x][i];      // = ew[e][d][f]
        __nv_bfloat16 hr = __float2bfloat16(w.x);
        __nv_bfloat16 lr = __float2bfloat16(w.x - __bfloat162float(hr));
        __nv_bfloat16 hi = __float2bfloat16(w.y);
        __nv_bfloat16 li = __float2bfloat16(w.y - __bfloat162float(hi));
        __nv_bfloat16 hn = __float2bfloat16(-w.y);
        __nv_bfloat16 ln = __float2bfloat16(-w.y - __bfloat162float(hn));
        size_t r0 = wb + (size_t)f * K2;
        size_t r1 = wb + (size_t)(Dm + f) * K2;
        g_Wh[r0 + d]      = hr;  g_Wl[r0 + d]      = lr;
        g_Wh[r0 + Dm + d] = hn;  g_Wl[r0 + Dm + d] = ln;
        g_Wh[r1 + d]      = hi;  g_Wl[r1 + d]      = li;
        g_Wh[r1 + Dm + d] = hr;  g_Wl[r1 + Dm + d] = lr;
    }
}

// ---------------- 6) mma.sync GEMM + fused scatter epilogue -------------------
__device__ __forceinline__ void load_chunk(int tid, int e, int bm, int bn,
                                           int c, uint32_t sbase) {
    int pass = c >> 5;                 // 0: Ah*Wh  1: Al*Wh  2: Ah*Wl
    int k0 = (c & 31) * BK;
    const __nv_bfloat16* Ab = (pass == 1 ? g_Al : g_Ah) + (size_t)e * KN * K2;
    const __nv_bfloat16* Wb = (pass == 2 ? g_Wl : g_Wh) + (size_t)e * K2 * K2;
#pragma unroll
    for (int j = 0; j < 8; j++) {
        int o = tid + j * 256;                 // 0..2047
        bool isA = o < 1024;
        int oo = isA ? o : o - 1024;
        int r = oo >> 3;                       // row 0..127
        int c16 = oo & 7;                      // 16B chunk in row
        const void* src = isA
            ? (const void*)(Ab + (size_t)(bm + r) * K2 + k0 + c16 * 8)
            : (const void*)(Wb + (size_t)(bn + r) * K2 + k0 + c16 * 8);
        uint32_t dst = sbase + (isA ? 0u : (uint32_t)A_TILE_B)
                     + swz(r * 128 + c16 * 16);
        asm volatile("cp.async.cg.shared.global [%0], [%1], 16;"
                     :: "r"(dst), "l"(src) : "memory");
    }
    asm volatile("cp.async.commit_group;" ::: "memory");
}

__global__ void __launch_bounds__(256) gemm_kernel(float* __restrict__ out) {
    extern __shared__ char smem[];
    const uint32_t SM_TILE = smem_u32(smem);
    const int tid  = threadIdx.x;
    const int wid  = tid >> 5;
    const int lane = tid & 31;
    const int e  = blockIdx.z;
    const int bm = blockIdx.y * BM;
    const int bn = blockIdx.x * BN;

    const int wm = (wid >> 1) * 32;            // warp M offset (4 warps)
    const int wn = (wid & 1) * 64;             // warp N offset (2 warps)

    float acc[2][8][4];
#pragma unroll
    for (int mt = 0; mt < 2; mt++)
#pragma unroll
        for (int nf = 0; nf < 8; nf++)
#pragma unroll
            for (int r = 0; r < 4; r++) acc[mt][nf][r] = 0.f;

    load_chunk(tid, e, bm, bn, 0, SM_TILE);
    load_chunk(tid, e, bm, bn, 1, SM_TILE + STAGE_BYTES);

    // ldmatrix lane addressing: row = base + (lane&15), kbyte += (lane>>4)*16
    const int lrow = lane & 15;
    const int lkb  = (lane >> 4) * 16;

    for (int i = 0; i < NCHUNK; i++) {
        uint32_t sbase = SM_TILE + (i % NSTAGE) * STAGE_BYTES;
        if (i < NCHUNK - 2)
            asm volatile("cp.async.wait_group 1;" ::: "memory");
        else
            asm volatile("cp.async.wait_group 0;" ::: "memory");
        __syncthreads();

        if (i + 2 < NCHUNK)
            load_chunk(tid, e, bm, bn, i + 2,
                       SM_TILE + ((i + 2) % NSTAGE) * STAGE_BYTES);

#pragma unroll
        for (int ks = 0; ks < 4; ks++) {
            uint32_t a[2][4], bbuf[4][4];
#pragma unroll
            for (int mt = 0; mt < 2; mt++) {
                uint32_t addr = sbase +
                    swz((wm + mt * 16 + lrow) * 128 + ks * 32 + lkb);
                ldsm4(a[mt], addr);
            }
#pragma unroll
            for (int nt = 0; nt < 4; nt++) {
                uint32_t addr = sbase + A_TILE_B +
                    swz((wn + nt * 16 + lrow) * 128 + ks * 32 + lkb);
                ldsm4(bbuf[nt], addr);
            }
#pragma unroll
            for (int mt = 0; mt < 2; mt++)
#pragma unroll
                for (int nt = 0; nt < 4; nt++) {
                    uint32_t b0[2] = { bbuf[nt][0], bbuf[nt][2] };
                    uint32_t b1[2] = { bbuf[nt][1], bbuf[nt][3] };
                    mma16816(acc[mt][nt * 2],     a[mt], b0);
                    mma16816(acc[mt][nt * 2 + 1], a[mt], b1);
                }
        }
        __syncthreads();
    }

    // fused epilogue: scale by score/count, atomic scatter into out
    const int g  = lane >> 2;
    const int tg = lane & 3;
#pragma unroll
    for (int mt = 0; mt < 2; mt++) {
#pragma unroll
        for (int half = 0; half < 2; half++) {
            int kk = bm + wm + mt * 16 + g + half * 8;     // expert-local row
            int t = g_tidx[kk * E + e];
            float s = g_tsc[kk * E + e];
            float scale = s / fmaxf(g_counts[t], 1.0f);
            float* obase = out + (size_t)t * K2;
#pragma unroll
            for (int nf = 0; nf < 8; nf++) {
#pragma unroll
                for (int cc = 0; cc < 2; cc++) {
                    int n = bn + wn + nf * 8 + tg * 2 + cc;
                    int f = n & (Dm - 1);
                    int im = n >> 10;
                    atomicAdd(obase + 2 * f + im,
                              acc[mt][nf][half * 2 + cc] * scale);
                }
            }
        }
    }
}

// ---------------- 7) ModReLU --------------------------------------------------
__global__ void finalize_kernel(float* __restrict__ out,
                                const float* __restrict__ bias) {
    size_t i = (size_t)blockIdx.x * blockDim.x + threadIdx.x;
    int d = (int)(i % Dm);
    float2 z = ((float2*)out)[i];
    float mag = sqrtf(z.x * z.x + z.y * z.y);
    float act = fmaxf(mag + bias[d], 0.0f);
    float inv = act / fmaxf(mag, 1e-8f);
    z.x *= inv; z.y *= inv;
    ((float2*)out)[i] = z;
}

// ---------------- 8) optional extras ------------------------------------------
__global__ void extras_kernel(float* __restrict__ out, int avail) {
    int i = blockIdx.x * blockDim.x + threadIdx.x;
    float* ex = out + RES_N;
    if (i < KN * E && i < avail)             ex[i] = (float)g_tidx[i];
    if (i < KN * E && KN * E + i < avail)    ex[KN * E + i] = g_tsc[i];
    if (i < BT    && 2 * KN * E + i < avail) ex[2 * KN * E + i] = g_counts[i];
}

// -------------------------------------------------------------------------------
extern "C" void kernel_launch(void* const* d_in, const int* in_sizes, int n_in,
                              void* d_out, int out_size) {
    const float* x    = (const float*)d_in[0];
    const float* gw   = (const float*)d_in[1];
    const float* ew   = (const float*)d_in[2];
    const float* bias = (const float*)d_in[3];
    float* out = (float*)d_out;

    cudaMemsetAsync(d_out, 0, (size_t)RES_N * sizeof(float), 0);

    gate_kernel<<<(BT * E) / 256, 256>>>(x, gw);

    cudaFuncSetAttribute(topk_kernel,
                         cudaFuncAttributeMaxDynamicSharedMemorySize, 131072);
    topk_kernel<<<E, 1024, 131072>>>();

    counts_zero_kernel<<<BT / 256, 256>>>();
    counts_add_kernel<<<(KN * E) / 256, 256>>>();

    build_A_kernel<<<E * KN, 256>>>(x);
    build_W_kernel<<<dim3(Dm / 32, Dm / 32, E), dim3(32, 8)>>>(ew);

    const int smem_bytes = NSTAGE * STAGE_BYTES;   // 96 KB
    cudaFuncSetAttribute(gemm_kernel,
                         cudaFuncAttributeMaxDynamicSharedMemorySize, smem_bytes);
    gemm_kernel<<<dim3(K2 / BN, KN / BM, E), 256, smem_bytes>>>(out);

    finalize_kernel<<<(BT * Dm) / 256, 256>>>(out, bias);

    if (out_size > RES_N) {
        int avail = out_size - RES_N;
        extras_kernel<<<(BT + 255) / 256, 256>>>(out, avail);
    }
}